// round 3
// baseline (speedup 1.0000x reference)
#include <cuda_runtime.h>
#include <cstdint>

// ---------------------------------------------------------------------------
// CrossAttentionDecoder:
//   x  (1024, 16, 512)  tokens
//   l  (1024, 128, 512) latents
//   q = x@Wq^T ; k = l@Wk^T ; v = l@Wv^T   (8 heads x 64)
//   scores = q k^T / 8, causal-latent mask: batch b sees j <= b%128
//   out = softmax(scores) v ; y = out@Wo^T + bo
//
// Pipeline (5 launches):
//   1. gemm q   (16384 x 512 x 512)
//   2. gemm k   (131072 x 512 x 512, row-masked)
//   3. gemm v   (same)
//   4. attention per (b,h): 8192 blocks, all-SMEM
//   5. gemm out + bias (16384 x 512 x 512)
// ---------------------------------------------------------------------------

#define NHEADS 8
#define DH 64
#define DIM 512
#define NLAT 128
#define NTOK 16
#define NB 1024            // true_batch * num_latents
#define QROWS (NB * NTOK)      // 16384
#define KVROWS (NB * NLAT)     // 131072

// Scratch (allocation-free rule: __device__ globals)
__device__ float g_q [QROWS  * DIM];   //  32 MB
__device__ float g_k [KVROWS * DIM];   // 256 MB
__device__ float g_v [KVROWS * DIM];   // 256 MB
__device__ float g_ao[QROWS  * DIM];   //  32 MB

// ---------------------------------------------------------------------------
// SGEMM  C[M,N] = A[M,K] @ B[N,K]^T (+bias), K = N = 512 fixed.
// BM=BN=128, BK=8, 256 threads, 8x8 microtile.
// MASKED: row tile y corresponds to batch b = y; only rows < (y&127)+1 are
// live (loads/FMAs/stores for dead rows skipped — garbage smem is never
// consumed by a stored accumulator row).
// ---------------------------------------------------------------------------
template<bool MASKED, bool BIAS>
__global__ __launch_bounds__(256)
void gemm_abt(const float* __restrict__ A, const float* __restrict__ B,
              const float* __restrict__ bias, float* __restrict__ C)
{
    __shared__ float As[8][128];
    __shared__ float Bs[8][128];

    const int tid = threadIdx.x;
    const int tx  = tid & 15;      // col group
    const int ty  = tid >> 4;      // row group
    const size_t m0 = (size_t)blockIdx.y * 128;
    const int    n0 = blockIdx.x * 128;
    const int limit = MASKED ? ((blockIdx.y & 127) + 1) : 128;

    const int lr = tid >> 1;          // 0..127: tile row (A) / tile col-row (B)
    const int lc = (tid & 1) * 4;     // 0 or 4

    const bool loadA  = (!MASKED) || (lr < limit);
    const bool active = (!MASKED) || (ty * 8 < limit);

    const float* Ap = A + (m0 + lr) * DIM + lc;
    const float* Bp = B + (size_t)(n0 + lr) * DIM + lc;

    float acc[8][8];
    #pragma unroll
    for (int i = 0; i < 8; i++)
        #pragma unroll
        for (int j = 0; j < 8; j++) acc[i][j] = 0.f;

    for (int kt = 0; kt < DIM; kt += 8) {
        if (loadA) {
            float4 a4 = *reinterpret_cast<const float4*>(Ap + kt);
            As[lc + 0][lr] = a4.x; As[lc + 1][lr] = a4.y;
            As[lc + 2][lr] = a4.z; As[lc + 3][lr] = a4.w;
        }
        {
            float4 b4 = *reinterpret_cast<const float4*>(Bp + kt);
            Bs[lc + 0][lr] = b4.x; Bs[lc + 1][lr] = b4.y;
            Bs[lc + 2][lr] = b4.z; Bs[lc + 3][lr] = b4.w;
        }
        __syncthreads();

        if (active) {
            #pragma unroll
            for (int k = 0; k < 8; k++) {
                float a[8], bb[8];
                *reinterpret_cast<float4*>(&a[0])  = *reinterpret_cast<float4*>(&As[k][ty * 8]);
                *reinterpret_cast<float4*>(&a[4])  = *reinterpret_cast<float4*>(&As[k][ty * 8 + 4]);
                *reinterpret_cast<float4*>(&bb[0]) = *reinterpret_cast<float4*>(&Bs[k][tx * 8]);
                *reinterpret_cast<float4*>(&bb[4]) = *reinterpret_cast<float4*>(&Bs[k][tx * 8 + 4]);
                #pragma unroll
                for (int i = 0; i < 8; i++)
                    #pragma unroll
                    for (int j = 0; j < 8; j++)
                        acc[i][j] = fmaf(a[i], bb[j], acc[i][j]);
            }
        }
        __syncthreads();
    }

    if (active) {
        float bv[8];
        #pragma unroll
        for (int j = 0; j < 8; j++)
            bv[j] = BIAS ? bias[n0 + tx * 8 + j] : 0.f;

        #pragma unroll
        for (int i = 0; i < 8; i++) {
            int r = ty * 8 + i;
            if (MASKED && r >= limit) break;
            float* crow = C + (m0 + r) * DIM + n0 + tx * 8;
            float vals[8];
            #pragma unroll
            for (int j = 0; j < 8; j++) vals[j] = acc[i][j] + bv[j];
            *reinterpret_cast<float4*>(crow)     = *reinterpret_cast<float4*>(&vals[0]);
            *reinterpret_cast<float4*>(crow + 4) = *reinterpret_cast<float4*>(&vals[4]);
        }
    }
}

// ---------------------------------------------------------------------------
// Attention: one block per (b, h). 128 threads.
// q (16x64) + k rows<L staged in SMEM -> scores -> softmax -> v reuses the
// k buffer -> PV -> write to interleaved (b, tok, h*64+d) layout for O-proj.
// ---------------------------------------------------------------------------
__global__ __launch_bounds__(128)
void attn_kernel(const float* __restrict__ qb, const float* __restrict__ kb,
                 const float* __restrict__ vb, float* __restrict__ ob)
{
    __shared__ float qs [16 * 68];   // stride 68 to dodge bank conflicts
    __shared__ float kvs[128 * 68];  // k, then reused for v
    __shared__ float ss [16 * 132];  // scores / probs
    __shared__ float rinv[16];

    const int tid = threadIdx.x;
    const int bh  = blockIdx.x;
    const int b   = bh >> 3;
    const int h   = bh & 7;
    const int L   = (b & 127) + 1;

    const float* qsrc = qb + (size_t)(b * NTOK) * DIM + h * DH;
    const float* ksrc = kb + (size_t)(b * NLAT) * DIM + h * DH;
    const float* vsrc = vb + (size_t)(b * NLAT) * DIM + h * DH;

    // stage q: 16 rows x 64 floats
    {
        int r = tid >> 3;
        int c = (tid & 7) * 8;
        float4 v0 = *reinterpret_cast<const float4*>(qsrc + (size_t)r * DIM + c);
        float4 v1 = *reinterpret_cast<const float4*>(qsrc + (size_t)r * DIM + c + 4);
        *reinterpret_cast<float4*>(qs + r * 68 + c)     = v0;
        *reinterpret_cast<float4*>(qs + r * 68 + c + 4) = v1;
    }
    // stage k rows < L
    for (int idx = tid; idx < L * 16; idx += 128) {
        int j = idx >> 4, c = (idx & 15) * 4;
        *reinterpret_cast<float4*>(kvs + j * 68 + c) =
            *reinterpret_cast<const float4*>(ksrc + (size_t)j * DIM + c);
    }
    __syncthreads();

    const int i = tid & 15;   // query row
    const int g = tid >> 4;   // 0..7

    // scores: thread covers 16 latent cols
    #pragma unroll 1
    for (int jj = 0; jj < 16; jj++) {
        int j = g * 16 + jj;
        if (j < L) {
            const float* qp = qs + i * 68;
            const float* kp = kvs + j * 68;
            float s = 0.f;
            #pragma unroll
            for (int d = 0; d < 64; d++) s = fmaf(qp[d], kp[d], s);
            ss[i * 132 + j] = s * 0.125f;   // dh^-0.5
        }
    }
    __syncthreads();

    // overwrite k buffer with v
    for (int idx = tid; idx < L * 16; idx += 128) {
        int j = idx >> 4, c = (idx & 15) * 4;
        *reinterpret_cast<float4*>(kvs + j * 68 + c) =
            *reinterpret_cast<const float4*>(vsrc + (size_t)j * DIM + c);
    }
    // softmax (unnormalized exp; 1/sum folded into PV epilogue)
    if (tid < 16) {
        float* row = ss + tid * 132;
        float m = row[0];
        for (int j = 1; j < L; j++) m = fmaxf(m, row[j]);
        float sum = 0.f;
        for (int j = 0; j < L; j++) { float e = __expf(row[j] - m); row[j] = e; sum += e; }
        rinv[tid] = 1.f / sum;
    }
    __syncthreads();

    // PV: thread (i, g) produces out[i][g*8 .. g*8+7]
    float acc[8];
    #pragma unroll
    for (int r = 0; r < 8; r++) acc[r] = 0.f;
    for (int j = 0; j < L; j++) {
        float p = ss[i * 132 + j];
        const float* vp = kvs + j * 68 + g * 8;
        #pragma unroll
        for (int r = 0; r < 8; r++) acc[r] = fmaf(p, vp[r], acc[r]);
    }
    const float inv = rinv[i];
    float* dst = ob + (size_t)(b * NTOK + i) * DIM + h * DH + g * 8;
    float4 o0 = make_float4(acc[0] * inv, acc[1] * inv, acc[2] * inv, acc[3] * inv);
    float4 o1 = make_float4(acc[4] * inv, acc[5] * inv, acc[6] * inv, acc[7] * inv);
    *reinterpret_cast<float4*>(dst)     = o0;
    *reinterpret_cast<float4*>(dst + 4) = o1;
}

// ---------------------------------------------------------------------------
extern "C" void kernel_launch(void* const* d_in, const int* in_sizes, int n_in,
                              void* d_out, int out_size)
{
    const float* x  = (const float*)d_in[0];
    const float* l  = (const float*)d_in[1];
    const float* Wq = (const float*)d_in[2];
    const float* Wk = (const float*)d_in[3];
    const float* Wv = (const float*)d_in[4];
    const float* Wo = (const float*)d_in[5];
    const float* bo = (const float*)d_in[6];
    float* out = (float*)d_out;

    void *pq, *pk, *pv, *pa;
    cudaGetSymbolAddress(&pq, g_q);
    cudaGetSymbolAddress(&pk, g_k);
    cudaGetSymbolAddress(&pv, g_v);
    cudaGetSymbolAddress(&pa, g_ao);
    float* q  = (float*)pq;
    float* k  = (float*)pk;
    float* v  = (float*)pv;
    float* ao = (float*)pa;

    dim3 blk(256);
    // q = x @ Wq^T
    gemm_abt<false, false><<<dim3(4, QROWS / 128), blk>>>(x, Wq, nullptr, q);
    // k/v = l @ W^T, masked to live latent rows
    gemm_abt<true, false><<<dim3(4, NB), blk>>>(l, Wk, nullptr, k);
    gemm_abt<true, false><<<dim3(4, NB), blk>>>(l, Wv, nullptr, v);
    // attention
    attn_kernel<<<NB * NHEADS, 128>>>(q, k, v, ao);
    // out = ao @ Wo^T + bo
    gemm_abt<false, true><<<dim3(4, QROWS / 128), blk>>>(ao, Wo, bo, out);
}

// round 4
// speedup vs baseline: 1.9918x; 1.9918x over previous
#include <cuda_runtime.h>
#include <cstdint>

// ---------------------------------------------------------------------------
// CrossAttentionDecoder, tf32 tensor-core GEMMs:
//   x (1024,16,512), l (1024,128,512), 8 heads x 64
//   q = x@Wq^T ; k = l@Wk^T ; v = l@Wv^T  (k/v masked: batch b uses rows <= b%128)
//   attn per (b,h), then out@Wo^T + bo
// ---------------------------------------------------------------------------

#define NHEADS 8
#define DH 64
#define DIM 512
#define NLAT 128
#define NTOK 16
#define NB 1024
#define QROWS (NB * NTOK)      // 16384
#define KVROWS (NB * NLAT)     // 131072

__device__ float g_q [QROWS  * DIM];
__device__ float g_k [KVROWS * DIM];
__device__ float g_v [KVROWS * DIM];
__device__ float g_ao[QROWS  * DIM];

__device__ __forceinline__ uint32_t f2tf32(float x) {
    uint32_t r;
    asm("cvt.rna.tf32.f32 %0, %1;" : "=r"(r) : "f"(x));
    return r;
}

__device__ __forceinline__ void mma_tf32(float* d, const uint32_t* a, const uint32_t* b) {
    asm volatile(
        "mma.sync.aligned.m16n8k8.row.col.f32.tf32.tf32.f32 "
        "{%0,%1,%2,%3}, {%4,%5,%6,%7}, {%8,%9}, {%0,%1,%2,%3};"
        : "+f"(d[0]), "+f"(d[1]), "+f"(d[2]), "+f"(d[3])
        : "r"(a[0]), "r"(a[1]), "r"(a[2]), "r"(a[3]), "r"(b[0]), "r"(b[1]));
}

// ---------------------------------------------------------------------------
// tf32 GEMM  C[M,N] = A[M,K] @ B[N,K]^T (+bias), K = N = 512.
// Block 128x128, BK=16, 256 threads = 8 warps as 4(M)x2(N); warp tile 32x64.
// MASKED: only rows < (blockIdx.y & 127)+1 are live.
// ---------------------------------------------------------------------------
template<bool MASKED, bool BIAS>
__global__ __launch_bounds__(256, 2)
void gemm_tf32(const float* __restrict__ A, const float* __restrict__ B,
               const float* __restrict__ bias, float* __restrict__ C)
{
    __shared__ uint32_t As[2][16][132];   // [stage][k][m]
    __shared__ uint32_t Bs[2][16][132];   // [stage][k][n]

    const int tid  = threadIdx.x;
    const int lane = tid & 31;
    const int warp = tid >> 5;
    const int wm   = warp >> 1;   // 0..3  (M tile of 32)
    const int wn   = warp & 1;    // 0..1  (N tile of 64)
    const size_t m0 = (size_t)blockIdx.y * 128;
    const int    n0 = blockIdx.x * 128;
    const int limit = MASKED ? ((blockIdx.y & 127) + 1) : 128;

    const int lr = tid >> 1;           // 0..127
    const int lc = (tid & 1) * 8;      // 0 or 8
    const bool loadA  = (!MASKED) || (lr < limit);
    const bool active = (!MASKED) || (wm * 32 < limit);

    const float* Ap = A + (m0 + lr) * DIM + lc;
    const float* Bp = B + (size_t)(n0 + lr) * DIM + lc;

    float acc[2][8][4];
    #pragma unroll
    for (int ma = 0; ma < 2; ma++)
        #pragma unroll
        for (int na = 0; na < 8; na++)
            #pragma unroll
            for (int r = 0; r < 4; r++) acc[ma][na][r] = 0.f;

    float ra[8], rb[8];

    // ---- prologue: stage 0 ----
    if (loadA) {
        float4 a0 = *reinterpret_cast<const float4*>(Ap);
        float4 a1 = *reinterpret_cast<const float4*>(Ap + 4);
        ra[0]=a0.x; ra[1]=a0.y; ra[2]=a0.z; ra[3]=a0.w;
        ra[4]=a1.x; ra[5]=a1.y; ra[6]=a1.z; ra[7]=a1.w;
    }
    {
        float4 b0 = *reinterpret_cast<const float4*>(Bp);
        float4 b1 = *reinterpret_cast<const float4*>(Bp + 4);
        rb[0]=b0.x; rb[1]=b0.y; rb[2]=b0.z; rb[3]=b0.w;
        rb[4]=b1.x; rb[5]=b1.y; rb[6]=b1.z; rb[7]=b1.w;
    }
    #pragma unroll
    for (int i = 0; i < 8; i++) {
        As[0][lc + i][lr] = f2tf32(ra[i]);
        Bs[0][lc + i][lr] = f2tf32(rb[i]);
    }
    __syncthreads();

    int cur = 0;
    const int c = lane & 3;
    const int r = lane >> 2;

    for (int kt = 16; kt <= DIM; kt += 16) {
        // global prefetch for next stage (skipped on last iter)
        if (kt < DIM) {
            if (loadA) {
                float4 a0 = *reinterpret_cast<const float4*>(Ap + kt);
                float4 a1 = *reinterpret_cast<const float4*>(Ap + kt + 4);
                ra[0]=a0.x; ra[1]=a0.y; ra[2]=a0.z; ra[3]=a0.w;
                ra[4]=a1.x; ra[5]=a1.y; ra[6]=a1.z; ra[7]=a1.w;
            }
            float4 b0 = *reinterpret_cast<const float4*>(Bp + kt);
            float4 b1 = *reinterpret_cast<const float4*>(Bp + kt + 4);
            rb[0]=b0.x; rb[1]=b0.y; rb[2]=b0.z; rb[3]=b0.w;
            rb[4]=b1.x; rb[5]=b1.y; rb[6]=b1.z; rb[7]=b1.w;
        }

        // compute current stage
        if (active) {
            #pragma unroll
            for (int kk = 0; kk < 16; kk += 8) {
                uint32_t af[2][4], bf[8][2];
                #pragma unroll
                for (int ma = 0; ma < 2; ma++) {
                    const int mb = wm * 32 + ma * 16;
                    af[ma][0] = As[cur][kk + c    ][mb + r];
                    af[ma][1] = As[cur][kk + c    ][mb + r + 8];
                    af[ma][2] = As[cur][kk + c + 4][mb + r];
                    af[ma][3] = As[cur][kk + c + 4][mb + r + 8];
                }
                #pragma unroll
                for (int na = 0; na < 8; na++) {
                    const int nb = wn * 64 + na * 8;
                    bf[na][0] = Bs[cur][kk + c    ][nb + r];
                    bf[na][1] = Bs[cur][kk + c + 4][nb + r];
                }
                #pragma unroll
                for (int ma = 0; ma < 2; ma++)
                    #pragma unroll
                    for (int na = 0; na < 8; na++)
                        mma_tf32(acc[ma][na], af[ma], bf[na]);
            }
        }

        if (kt < DIM) {
            const int nxt = cur ^ 1;   // last computed 2 iters ago; sync below covers
            #pragma unroll
            for (int i = 0; i < 8; i++) {
                As[nxt][lc + i][lr] = f2tf32(ra[i]);
                Bs[nxt][lc + i][lr] = f2tf32(rb[i]);
            }
            __syncthreads();
            cur = nxt;
        }
    }

    // ---- epilogue ----
    if (active) {
        const int cq = (lane & 3) * 2;
        #pragma unroll
        for (int ma = 0; ma < 2; ma++) {
            const int row0 = wm * 32 + ma * 16 + r;
            const int row1 = row0 + 8;
            #pragma unroll
            for (int na = 0; na < 8; na++) {
                const int col = n0 + wn * 64 + na * 8 + cq;
                float b0 = 0.f, b1 = 0.f;
                if (BIAS) { b0 = bias[col]; b1 = bias[col + 1]; }
                if ((!MASKED) || (row0 < limit)) {
                    float2 o = make_float2(acc[ma][na][0] + b0, acc[ma][na][1] + b1);
                    *reinterpret_cast<float2*>(C + (m0 + row0) * DIM + col) = o;
                }
                if ((!MASKED) || (row1 < limit)) {
                    float2 o = make_float2(acc[ma][na][2] + b0, acc[ma][na][3] + b1);
                    *reinterpret_cast<float2*>(C + (m0 + row1) * DIM + col) = o;
                }
            }
        }
    }
}

// ---------------------------------------------------------------------------
// Attention: one block per (b, h), 128 threads.
// Register-blocked scores (float4 K loads), parallel softmax, float4 PV.
// ---------------------------------------------------------------------------
__global__ __launch_bounds__(128)
void attn_kernel(const float* __restrict__ qb, const float* __restrict__ kb,
                 const float* __restrict__ vb, float* __restrict__ ob)
{
    __shared__ float qs [16 * 68];
    __shared__ float kvs[128 * 68];   // k, then reused for v
    __shared__ float ss [16 * 132];
    __shared__ float red[16][9];      // per-(row, group) partials
    __shared__ float rowmax[16], rinv[16];

    const int tid = threadIdx.x;
    const int bh  = blockIdx.x;
    const int b   = bh >> 3;
    const int h   = bh & 7;
    const int L   = (b & 127) + 1;

    const float* qsrc = qb + (size_t)(b * NTOK) * DIM + h * DH;
    const float* ksrc = kb + (size_t)(b * NLAT) * DIM + h * DH;
    const float* vsrc = vb + (size_t)(b * NLAT) * DIM + h * DH;

    // stage q (16 x 64)
    {
        int rr = tid >> 3;
        int cc = (tid & 7) * 8;
        float4 v0 = *reinterpret_cast<const float4*>(qsrc + (size_t)rr * DIM + cc);
        float4 v1 = *reinterpret_cast<const float4*>(qsrc + (size_t)rr * DIM + cc + 4);
        *reinterpret_cast<float4*>(qs + rr * 68 + cc)     = v0;
        *reinterpret_cast<float4*>(qs + rr * 68 + cc + 4) = v1;
    }
    // stage k rows < L
    for (int idx = tid; idx < L * 16; idx += 128) {
        int j = idx >> 4, cc = (idx & 15) * 4;
        *reinterpret_cast<float4*>(kvs + j * 68 + cc) =
            *reinterpret_cast<const float4*>(ksrc + (size_t)j * DIM + cc);
    }
    __syncthreads();

    const int i = tid & 15;   // query row
    const int g = tid >> 4;   // 0..7 (latent group of 16 / output dim group of 8)

    // scores: thread (i,g) computes s[i][g*16 .. g*16+15]
    float sc[16];
    #pragma unroll
    for (int jj = 0; jj < 16; jj++) sc[jj] = 0.f;
    {
        const float* qp = qs + i * 68;
        #pragma unroll 4
        for (int d = 0; d < 64; d += 4) {
            const float4 q4 = *reinterpret_cast<const float4*>(qp + d);
            #pragma unroll
            for (int jj = 0; jj < 16; jj++) {
                const float4 k4 = *reinterpret_cast<const float4*>(kvs + (g * 16 + jj) * 68 + d);
                sc[jj] = fmaf(q4.x, k4.x, fmaf(q4.y, k4.y, fmaf(q4.z, k4.z, fmaf(q4.w, k4.w, sc[jj]))));
            }
        }
    }
    // scale, store, partial max
    {
        float m = -1e30f;
        #pragma unroll
        for (int jj = 0; jj < 16; jj++) {
            int j = g * 16 + jj;
            if (j < L) {
                float s = sc[jj] * 0.125f;
                ss[i * 132 + j] = s;
                m = fmaxf(m, s);
            }
        }
        red[i][g] = m;
    }
    __syncthreads();

    if (tid < 16) {
        float m = red[tid][0];
        #pragma unroll
        for (int t = 1; t < 8; t++) m = fmaxf(m, red[tid][t]);
        rowmax[tid] = m;
    }
    // overwrite k buffer with v (scores already consumed kvs)
    for (int idx = tid; idx < L * 16; idx += 128) {
        int j = idx >> 4, cc = (idx & 15) * 4;
        *reinterpret_cast<float4*>(kvs + j * 68 + cc) =
            *reinterpret_cast<const float4*>(vsrc + (size_t)j * DIM + cc);
    }
    __syncthreads();

    // exp + partial sum (parallel over g)
    {
        const float m = rowmax[i];
        float s = 0.f;
        #pragma unroll
        for (int jj = 0; jj < 16; jj++) {
            int j = g * 16 + jj;
            if (j < L) {
                float e = __expf(ss[i * 132 + j] - m);
                ss[i * 132 + j] = e;
                s += e;
            }
        }
        red[i][g] = s;
    }
    __syncthreads();
    if (tid < 16) {
        float s = red[tid][0];
        #pragma unroll
        for (int t = 1; t < 8; t++) s += red[tid][t];
        rinv[tid] = 1.f / s;
    }
    __syncthreads();

    // PV: thread (i,g) -> out[i][g*8 .. g*8+7]
    float acc[8];
    #pragma unroll
    for (int rr = 0; rr < 8; rr++) acc[rr] = 0.f;
    for (int j = 0; j < L; j++) {
        const float p = ss[i * 132 + j];
        const float4 v0 = *reinterpret_cast<const float4*>(kvs + j * 68 + g * 8);
        const float4 v1 = *reinterpret_cast<const float4*>(kvs + j * 68 + g * 8 + 4);
        acc[0] = fmaf(p, v0.x, acc[0]); acc[1] = fmaf(p, v0.y, acc[1]);
        acc[2] = fmaf(p, v0.z, acc[2]); acc[3] = fmaf(p, v0.w, acc[3]);
        acc[4] = fmaf(p, v1.x, acc[4]); acc[5] = fmaf(p, v1.y, acc[5]);
        acc[6] = fmaf(p, v1.z, acc[6]); acc[7] = fmaf(p, v1.w, acc[7]);
    }
    const float inv = rinv[i];
    float* dst = ob + (size_t)(b * NTOK + i) * DIM + h * DH + g * 8;
    *reinterpret_cast<float4*>(dst) =
        make_float4(acc[0] * inv, acc[1] * inv, acc[2] * inv, acc[3] * inv);
    *reinterpret_cast<float4*>(dst + 4) =
        make_float4(acc[4] * inv, acc[5] * inv, acc[6] * inv, acc[7] * inv);
}

// ---------------------------------------------------------------------------
extern "C" void kernel_launch(void* const* d_in, const int* in_sizes, int n_in,
                              void* d_out, int out_size)
{
    const float* x  = (const float*)d_in[0];
    const float* l  = (const float*)d_in[1];
    const float* Wq = (const float*)d_in[2];
    const float* Wk = (const float*)d_in[3];
    const float* Wv = (const float*)d_in[4];
    const float* Wo = (const float*)d_in[5];
    const float* bo = (const float*)d_in[6];
    float* out = (float*)d_out;

    void *pq, *pk, *pv, *pa;
    cudaGetSymbolAddress(&pq, g_q);
    cudaGetSymbolAddress(&pk, g_k);
    cudaGetSymbolAddress(&pv, g_v);
    cudaGetSymbolAddress(&pa, g_ao);
    float* q  = (float*)pq;
    float* k  = (float*)pk;
    float* v  = (float*)pv;
    float* ao = (float*)pa;

    dim3 blk(256);
    gemm_tf32<false, false><<<dim3(4, QROWS / 128), blk>>>(x, Wq, nullptr, q);
    gemm_tf32<true,  false><<<dim3(4, NB), blk>>>(l, Wk, nullptr, k);
    gemm_tf32<true,  false><<<dim3(4, NB), blk>>>(l, Wv, nullptr, v);
    attn_kernel<<<NB * NHEADS, 128>>>(q, k, v, ao);
    gemm_tf32<false, true><<<dim3(4, QROWS / 128), blk>>>(ao, Wo, bo, out);
}

// round 6
// speedup vs baseline: 2.3700x; 1.1898x over previous
#include <cuda_runtime.h>
#include <cstdint>

// ---------------------------------------------------------------------------
// CrossAttentionDecoder, tf32 mma.sync GEMMs with 64-bit paired fragment LDS:
//   x (1024,16,512), l (1024,128,512), 8 heads x 64
//   q = x@Wq^T ; k = l@Wk^T ; v = l@Wv^T  (masked: batch b uses rows <= b%128)
//   attn per (b,h), then out@Wo^T + bo
// ---------------------------------------------------------------------------

#define NHEADS 8
#define DH 64
#define DIM 512
#define NLAT 128
#define NTOK 16
#define NB 1024
#define QROWS (NB * NTOK)      // 16384
#define KVROWS (NB * NLAT)     // 131072

__device__ float g_q [QROWS  * DIM];
__device__ float g_k [KVROWS * DIM];
__device__ float g_v [KVROWS * DIM];
__device__ float g_ao[QROWS  * DIM];

__device__ __forceinline__ uint32_t f2tf32(float x) {
    uint32_t r;
    asm("cvt.rna.tf32.f32 %0, %1;" : "=r"(r) : "f"(x));
    return r;
}

__device__ __forceinline__ void mma_tf32(float* d, const uint32_t* a, const uint32_t* b) {
    asm volatile(
        "mma.sync.aligned.m16n8k8.row.col.f32.tf32.tf32.f32 "
        "{%0,%1,%2,%3}, {%4,%5,%6,%7}, {%8,%9}, {%0,%1,%2,%3};"
        : "+f"(d[0]), "+f"(d[1]), "+f"(d[2]), "+f"(d[3])
        : "r"(a[0]), "r"(a[1]), "r"(a[2]), "r"(a[3]), "r"(b[0]), "r"(b[1]));
}

// ---------------------------------------------------------------------------
// Packed smem layout for a 128x16 tf32 tile:
//   element (x, k): s = k>>3, c = k&3, h = (k>>2)&1
//   word offset = s*1040 + c*260 + x*2 + h          (plane pad: 130 x-entries)
// Fragment pair (k=c, k=c+4) at row x  ->  one aligned LDS.64.
// Stage size = 2080 words = 8320 B per tile.
// ---------------------------------------------------------------------------
#define TILE_W 2080

// stage one 128x16 tile (rows < limit) from gmem into packed layout.
// Each thread handles float4 #tid and #(tid+256) of the 512 float4s.
// STS pattern is conflict-free: bank = 16s + 4e + 2m + h covers all 32.
__device__ __forceinline__ void stage_ld(const float* __restrict__ src, int tid,
                                         int limit, float4* pv) {
    #pragma unroll
    for (int j = 0; j < 2; j++) {
        const int idx = tid + j * 256;
        const int x   = idx >> 2;
        const int kq  = idx & 3;
        if (x < limit)
            pv[j] = *reinterpret_cast<const float4*>(src + (size_t)x * DIM + kq * 4);
    }
}
__device__ __forceinline__ void stage_st(uint32_t* __restrict__ dst, int tid,
                                         int limit, const float4* pv) {
    #pragma unroll
    for (int j = 0; j < 2; j++) {
        const int idx = tid + j * 256;
        const int x   = idx >> 2;
        const int kq  = idx & 3;        // s = kq>>1, h = kq&1, c = element index
        if (x < limit) {
            uint32_t base = (uint32_t)(kq >> 1) * 1040 + x * 2 + (kq & 1);
            dst[base      ] = f2tf32(pv[j].x);
            dst[base + 260] = f2tf32(pv[j].y);
            dst[base + 520] = f2tf32(pv[j].z);
            dst[base + 780] = f2tf32(pv[j].w);
        }
    }
}

// ---------------------------------------------------------------------------
// tf32 GEMM  C[M,N] = A[M,K] @ B[N,K]^T (+bias), K = N = 512.
// Block 128x128, BK=16 double-buffered, 256 threads = 8 warps (4M x 2N).
// MASKED: only rows < (blockIdx.y & 127)+1 are live.
// ---------------------------------------------------------------------------
template<bool MASKED, bool BIAS>
__global__ __launch_bounds__(256, 2)
void gemm_tf32(const float* __restrict__ A, const float* __restrict__ B,
               const float* __restrict__ bias, float* __restrict__ C)
{
    __shared__ __align__(16) uint32_t Abuf[2][TILE_W];
    __shared__ __align__(16) uint32_t Bbuf[2][TILE_W];

    const int tid  = threadIdx.x;
    const int lane = tid & 31;
    const int warp = tid >> 5;
    const int wm   = warp >> 1;   // 0..3  (M tile of 32)
    const int wn   = warp & 1;    // 0..1  (N tile of 64)
    const size_t m0 = (size_t)blockIdx.y * 128;
    const int    n0 = blockIdx.x * 128;
    const int limit = MASKED ? ((blockIdx.y & 127) + 1) : 128;
    const bool active = (!MASKED) || (wm * 32 < limit);

    const int r = lane >> 2;      // 0..7
    const int c = lane & 3;       // 0..3

    float acc[2][8][4];
    #pragma unroll
    for (int ma = 0; ma < 2; ma++)
        #pragma unroll
        for (int na = 0; na < 8; na++)
            #pragma unroll
            for (int q = 0; q < 4; q++) acc[ma][na][q] = 0.f;

    const float* Ag = A + m0 * DIM;
    const float* Bg = B + (size_t)n0 * DIM;

    float4 pa[2], pb[2];
    // prologue: stage k-slab 0
    stage_ld(Ag, tid, limit, pa);
    stage_ld(Bg, tid, 128,   pb);
    stage_st(Abuf[0], tid, limit, pa);
    stage_st(Bbuf[0], tid, 128,   pb);
    __syncthreads();

    #pragma unroll 1
    for (int it = 0; it < 32; it++) {
        const int buf = it & 1;
        // prefetch next slab
        if (it + 1 < 32) {
            stage_ld(Ag + (it + 1) * 16, tid, limit, pa);
            stage_ld(Bg + (it + 1) * 16, tid, 128,   pb);
        }
        // compute current slab
        if (active) {
            #pragma unroll
            for (int s = 0; s < 2; s++) {
                const uint32_t* Ab = &Abuf[buf][s * 1040 + c * 260];
                const uint32_t* Bb = &Bbuf[buf][s * 1040 + c * 260];
                uint32_t af[2][4];
                #pragma unroll
                for (int ma = 0; ma < 2; ma++) {
                    const int mb = wm * 32 + ma * 16;
                    const uint2 u0 = *reinterpret_cast<const uint2*>(Ab + (mb + r) * 2);
                    const uint2 u1 = *reinterpret_cast<const uint2*>(Ab + (mb + r + 8) * 2);
                    af[ma][0] = u0.x; af[ma][1] = u1.x; af[ma][2] = u0.y; af[ma][3] = u1.y;
                }
                #pragma unroll
                for (int na = 0; na < 8; na++) {
                    const int nb = wn * 64 + na * 8;
                    const uint2 bv = *reinterpret_cast<const uint2*>(Bb + (nb + r) * 2);
                    uint32_t bf[2] = { bv.x, bv.y };
                    mma_tf32(acc[0][na], af[0], bf);
                    mma_tf32(acc[1][na], af[1], bf);
                }
            }
        }
        if (it + 1 < 32) {
            stage_st(Abuf[buf ^ 1], tid, limit, pa);
            stage_st(Bbuf[buf ^ 1], tid, 128,   pb);
            __syncthreads();
        }
    }

    // ---- epilogue ----
    if (active) {
        const int cq = c * 2;
        #pragma unroll
        for (int ma = 0; ma < 2; ma++) {
            const int row0 = wm * 32 + ma * 16 + r;
            const int row1 = row0 + 8;
            #pragma unroll
            for (int na = 0; na < 8; na++) {
                const int col = n0 + wn * 64 + na * 8 + cq;
                float b0 = 0.f, b1 = 0.f;
                if (BIAS) { b0 = bias[col]; b1 = bias[col + 1]; }
                if ((!MASKED) || (row0 < limit)) {
                    float2 o = make_float2(acc[ma][na][0] + b0, acc[ma][na][1] + b1);
                    *reinterpret_cast<float2*>(C + (m0 + row0) * DIM + col) = o;
                }
                if ((!MASKED) || (row1 < limit)) {
                    float2 o = make_float2(acc[ma][na][2] + b0, acc[ma][na][3] + b1);
                    *reinterpret_cast<float2*>(C + (m0 + row1) * DIM + col) = o;
                }
            }
        }
    }
}

// ---------------------------------------------------------------------------
// Attention: one block per (b, h), 128 threads (unchanged from R4: 164us).
// ---------------------------------------------------------------------------
__global__ __launch_bounds__(128)
void attn_kernel(const float* __restrict__ qb, const float* __restrict__ kb,
                 const float* __restrict__ vb, float* __restrict__ ob)
{
    __shared__ float qs [16 * 68];
    __shared__ float kvs[128 * 68];
    __shared__ float ss [16 * 132];
    __shared__ float red[16][9];
    __shared__ float rowmax[16], rinv[16];

    const int tid = threadIdx.x;
    const int bh  = blockIdx.x;
    const int b   = bh >> 3;
    const int h   = bh & 7;
    const int L   = (b & 127) + 1;

    const float* qsrc = qb + (size_t)(b * NTOK) * DIM + h * DH;
    const float* ksrc = kb + (size_t)(b * NLAT) * DIM + h * DH;
    const float* vsrc = vb + (size_t)(b * NLAT) * DIM + h * DH;

    {
        int rr = tid >> 3;
        int cc = (tid & 7) * 8;
        float4 v0 = *reinterpret_cast<const float4*>(qsrc + (size_t)rr * DIM + cc);
        float4 v1 = *reinterpret_cast<const float4*>(qsrc + (size_t)rr * DIM + cc + 4);
        *reinterpret_cast<float4*>(qs + rr * 68 + cc)     = v0;
        *reinterpret_cast<float4*>(qs + rr * 68 + cc + 4) = v1;
    }
    for (int idx = tid; idx < L * 16; idx += 128) {
        int j = idx >> 4, cc = (idx & 15) * 4;
        *reinterpret_cast<float4*>(kvs + j * 68 + cc) =
            *reinterpret_cast<const float4*>(ksrc + (size_t)j * DIM + cc);
    }
    __syncthreads();

    const int i = tid & 15;
    const int g = tid >> 4;

    float sc[16];
    #pragma unroll
    for (int jj = 0; jj < 16; jj++) sc[jj] = 0.f;
    {
        const float* qp = qs + i * 68;
        #pragma unroll 4
        for (int d = 0; d < 64; d += 4) {
            const float4 q4 = *reinterpret_cast<const float4*>(qp + d);
            #pragma unroll
            for (int jj = 0; jj < 16; jj++) {
                const float4 k4 = *reinterpret_cast<const float4*>(kvs + (g * 16 + jj) * 68 + d);
                sc[jj] = fmaf(q4.x, k4.x, fmaf(q4.y, k4.y, fmaf(q4.z, k4.z, fmaf(q4.w, k4.w, sc[jj]))));
            }
        }
    }
    {
        float m = -1e30f;
        #pragma unroll
        for (int jj = 0; jj < 16; jj++) {
            int j = g * 16 + jj;
            if (j < L) {
                float s = sc[jj] * 0.125f;
                ss[i * 132 + j] = s;
                m = fmaxf(m, s);
            }
        }
        red[i][g] = m;
    }
    __syncthreads();

    if (tid < 16) {
        float m = red[tid][0];
        #pragma unroll
        for (int t = 1; t < 8; t++) m = fmaxf(m, red[tid][t]);
        rowmax[tid] = m;
    }
    for (int idx = tid; idx < L * 16; idx += 128) {
        int j = idx >> 4, cc = (idx & 15) * 4;
        *reinterpret_cast<float4*>(kvs + j * 68 + cc) =
            *reinterpret_cast<const float4*>(vsrc + (size_t)j * DIM + cc);
    }
    __syncthreads();

    {
        const float m = rowmax[i];
        float s = 0.f;
        #pragma unroll
        for (int jj = 0; jj < 16; jj++) {
            int j = g * 16 + jj;
            if (j < L) {
                float e = __expf(ss[i * 132 + j] - m);
                ss[i * 132 + j] = e;
                s += e;
            }
        }
        red[i][g] = s;
    }
    __syncthreads();
    if (tid < 16) {
        float s = red[tid][0];
        #pragma unroll
        for (int t = 1; t < 8; t++) s += red[tid][t];
        rinv[tid] = 1.f / s;
    }
    __syncthreads();

    float acc[8];
    #pragma unroll
    for (int rr = 0; rr < 8; rr++) acc[rr] = 0.f;
    for (int j = 0; j < L; j++) {
        const float p = ss[i * 132 + j];
        const float4 v0 = *reinterpret_cast<const float4*>(kvs + j * 68 + g * 8);
        const float4 v1 = *reinterpret_cast<const float4*>(kvs + j * 68 + g * 8 + 4);
        acc[0] = fmaf(p, v0.x, acc[0]); acc[1] = fmaf(p, v0.y, acc[1]);
        acc[2] = fmaf(p, v0.z, acc[2]); acc[3] = fmaf(p, v0.w, acc[3]);
        acc[4] = fmaf(p, v1.x, acc[4]); acc[5] = fmaf(p, v1.y, acc[5]);
        acc[6] = fmaf(p, v1.z, acc[6]); acc[7] = fmaf(p, v1.w, acc[7]);
    }
    const float inv = rinv[i];
    float* dst = ob + (size_t)(b * NTOK + i) * DIM + h * DH + g * 8;
    *reinterpret_cast<float4*>(dst) =
        make_float4(acc[0] * inv, acc[1] * inv, acc[2] * inv, acc[3] * inv);
    *reinterpret_cast<float4*>(dst + 4) =
        make_float4(acc[4] * inv, acc[5] * inv, acc[6] * inv, acc[7] * inv);
}

// ---------------------------------------------------------------------------
extern "C" void kernel_launch(void* const* d_in, const int* in_sizes, int n_in,
                              void* d_out, int out_size)
{
    const float* x  = (const float*)d_in[0];
    const float* l  = (const float*)d_in[1];
    const float* Wq = (const float*)d_in[2];
    const float* Wk = (const float*)d_in[3];
    const float* Wv = (const float*)d_in[4];
    const float* Wo = (const float*)d_in[5];
    const float* bo = (const float*)d_in[6];
    float* out = (float*)d_out;

    void *pq, *pk, *pv, *pa;
    cudaGetSymbolAddress(&pq, g_q);
    cudaGetSymbolAddress(&pk, g_k);
    cudaGetSymbolAddress(&pv, g_v);
    cudaGetSymbolAddress(&pa, g_ao);
    float* q  = (float*)pq;
    float* k  = (float*)pk;
    float* v  = (float*)pv;
    float* ao = (float*)pa;

    dim3 blk(256);
    gemm_tf32<false, false><<<dim3(4, QROWS / 128), blk>>>(x, Wq, nullptr, q);
    gemm_tf32<true,  false><<<dim3(4, NB), blk>>>(l, Wk, nullptr, k);
    gemm_tf32<true,  false><<<dim3(4, NB), blk>>>(l, Wv, nullptr, v);
    attn_kernel<<<NB * NHEADS, 128>>>(q, k, v, ao);
    gemm_tf32<false, true><<<dim3(4, QROWS / 128), blk>>>(ao, Wo, bo, out);
}